// round 11
// baseline (speedup 1.0000x reference)
#include <cuda_runtime.h>
#include <cfloat>

// xp: (32, 64, 64, 512) fp32, m innermost. out: (32, 48*512), bin = iw*6+ih.
// Resize is identity. Row bins: 8 rows each. Col edges: {0,11,21,32,43,53,64}.
//
// R11: R3's exact inner loop + the R9 tail idea with R9's failure mode fixed.
// R9 regressed (78->72.7% DRAM) because its 1D remap made ih vary FASTEST:
// consecutive block ids read the same image row-band 22KB apart, colliding on
// L2 slices/DRAM banks. Here b varies fastest -> consecutive ids touch
// DIFFERENT images (8MB apart): more dispersion than even R3's 2D order.
// Wide bins (nc=11, ih 0/2/3/5; 1024 blocks) launch first, narrow (nc=10,
// ih 1/4; 512 blocks) last, so the ~352-block drain wave is all-narrow
// (~9% shorter stragglers). nc is compile-time per group.

#define B_DIM 32
#define W_DIM 64
#define H_DIM 64
#define M_DIM 512
#define W_BINS 8
#define H_BINS 6
#define M4 (M_DIM / 4)            // 128 float4 lanes per (b,r,c)
#define ROW_STRIDE (H_DIM * M4)   // float4 elems per image row
#define N_WIDE (B_DIM * W_BINS * 4)   // 1024 wide blocks

__constant__ int IH_WIDE[4]   = {0, 2, 3, 5};   // c1: 0,21,32,53  (width 11)
__constant__ int IH_NARROW[2] = {1, 4};         // c1: 11,43       (width 10)
__constant__ int C_EDGE[H_BINS + 1] = {0, 11, 21, 32, 43, 53, 64};

static __device__ __forceinline__ float4 fmax4(float4 a, float4 b) {
    a.x = fmaxf(a.x, b.x);
    a.y = fmaxf(a.y, b.y);
    a.z = fmaxf(a.z, b.z);
    a.w = fmaxf(a.w, b.w);
    return a;
}

template <int NC>
static __device__ __forceinline__ float4
reduce_bin(const float4* __restrict__ base) {
    float4 acc = make_float4(-FLT_MAX, -FLT_MAX, -FLT_MAX, -FLT_MAX);
    // 8 rows as 4 row-pairs; per pair 2*NC independent 16B loads in flight.
    #pragma unroll 1
    for (int rp = 0; rp < 4; ++rp) {
        const float4* r0 = base + (size_t)(2 * rp) * ROW_STRIDE;
        const float4* r1 = r0 + ROW_STRIDE;
        #pragma unroll
        for (int c = 0; c < NC; ++c) {
            float4 va = __ldcs(r0 + (size_t)c * M4);
            float4 vb = __ldcs(r1 + (size_t)c * M4);
            acc = fmax4(acc, fmax4(va, vb));
        }
    }
    return acc;
}

// 1D grid, 1536 blocks. b fastest within each group (max address dispersion
// between concurrent ids); wide group [0,1024), narrow group [1024,1536).
__global__ __launch_bounds__(M4, 8)
void adaptive_maxpool_kernel(const float4* __restrict__ x4,
                             float4* __restrict__ out4) {
    const int fid = blockIdx.x;
    const int t = threadIdx.x;        // 0..127

    int b, iw, ih;
    bool wide;
    if (fid < N_WIDE) {
        wide = true;
        b = fid & 31;                 // b fastest
        const int rest = fid >> 5;    // 0..31
        iw = rest & 7;
        ih = IH_WIDE[rest >> 3];
    } else {
        wide = false;
        const int v = fid - N_WIDE;   // 0..511
        b = v & 31;                   // b fastest
        const int rest = v >> 5;      // 0..15
        iw = rest & 7;
        ih = IH_NARROW[rest >> 3];
    }

    const int r1 = iw * (W_DIM / W_BINS);   // 8 rows per bin
    const int c1 = C_EDGE[ih];

    const float4* base =
        x4 + ((size_t)(b * W_DIM + r1) * H_DIM + c1) * M4 + t;

    float4 acc = wide ? reduce_bin<11>(base) : reduce_bin<10>(base);

    const int bin = iw * H_BINS + ih;
    out4[((size_t)b * (W_BINS * H_BINS) + bin) * M4 + t] = acc;
}

extern "C" void kernel_launch(void* const* d_in, const int* in_sizes, int n_in,
                              void* d_out, int out_size) {
    (void)in_sizes; (void)n_in; (void)out_size;
    const float4* x4 = (const float4*)d_in[0];
    float4* o4 = (float4*)d_out;

    adaptive_maxpool_kernel<<<W_BINS * H_BINS * B_DIM, M4>>>(x4, o4);
}